// round 14
// baseline (speedup 1.0000x reference)
#include <cuda_runtime.h>
#include <stdint.h>

#define CC   128
#define CI   32
#define HH   128
#define WW   256
#define BB   8
#define HW   (HH*WW)

// Precomputed parameters (filled by prep kernel each launch; deterministic).
__device__ uint32_t g_w1m[CI][4];
__device__ float    g_inv1[CI], g_bb1[CI];
__device__ uint32_t g_w2m[CI][9];
__device__ float    g_inv2[CI], g_bb2[CI];
__device__ uint32_t g_w3m[CC];
__device__ float    g_inv3[CC], g_bb3[CC];

// Scratch: h1 binarized activations, 32 channels packed per pixel. 1 MB.
__device__ uint32_t g_h1b[BB * HW];

// ---------------------------------------------------------------------------
// Prep: ONE mask word per warp (544 words over 68 blocks x 8 warps).
// ---------------------------------------------------------------------------
__global__ void __launch_bounds__(256) prep_kernel(
    const float* __restrict__ w1, const float* __restrict__ g1,
    const float* __restrict__ b1, const float* __restrict__ m1, const float* __restrict__ v1,
    const float* __restrict__ w2, const float* __restrict__ g2,
    const float* __restrict__ b2, const float* __restrict__ m2, const float* __restrict__ v2,
    const float* __restrict__ w3, const float* __restrict__ g3,
    const float* __restrict__ b3, const float* __restrict__ m3, const float* __restrict__ v3)
{
    int tid  = threadIdx.x;
    int lane = tid & 31;
    int gw   = blockIdx.x * 8 + (tid >> 5);   // global word id 0..543

    if (gw < 128) {
        int oc = gw >> 2, j = gw & 3;
        uint32_t m = __ballot_sync(0xffffffffu, w1[oc * CC + j * 32 + lane] > 0.f);
        if (lane == 0) g_w1m[oc][j] = m;
    } else if (gw < 416) {
        int idx = gw - 128;
        int oc = idx / 9, t9 = idx - oc * 9;
        uint32_t m = __ballot_sync(0xffffffffu, w2[oc * (CI * 9) + lane * 9 + t9] > 0.f);
        if (lane == 0) g_w2m[oc][t9] = m;
    } else if (gw < 544) {
        int c = gw - 416;
        uint32_t m = __ballot_sync(0xffffffffu, w3[c * CI + lane] > 0.f);
        if (lane == 0) g_w3m[c] = m;
    }

    if (blockIdx.x == 0) {
        if (tid < CI) {
            float inv = __fdiv_rn(g1[tid], __fsqrt_rn(__fadd_rn(v1[tid], 1e-5f)));
            g_inv1[tid] = inv;
            g_bb1[tid]  = __fadd_rn(b1[tid], -__fmul_rn(m1[tid], inv));
        } else if (tid >= 64 && tid < 64 + CI) {
            int t = tid - 64;
            float inv = __fdiv_rn(g2[t], __fsqrt_rn(__fadd_rn(v2[t], 1e-5f)));
            g_inv2[t] = inv;
            g_bb2[t]  = __fadd_rn(b2[t], -__fmul_rn(m2[t], inv));
        } else if (tid >= 128) {
            int t = tid - 128;
            float inv = __fdiv_rn(g3[t], __fsqrt_rn(__fadd_rn(v3[t], 1e-5f)));
            g_inv3[t] = inv;
            g_bb3[t]  = __fadd_rn(b3[t], -__fmul_rn(m3[t], inv));
        }
    }
}

// ---------------------------------------------------------------------------
// Combined stage kernel, 2048 x 64-thread blocks.
//   blocks [0,1024):    MAIN part for batches [main_b0, main_b0+2):
//     tile 32x2 px, 1 px/thread: conv2 (3x3 on h1 masks, zero-pad) + bn+sign
//     -> h2b in registers -> conv3+bn+prelu+residual+prelu stream.
//     x reads are L2 hits (x chunk was loaded by the PREVIOUS launch's conv1
//     part; working set stays < L2).
//   blocks [1024,2048):  CONV1 part for batches [conv_b0, conv_b0+2):
//     1 px/thread conv1 (1x1, 128->32) + bn + sign -> g_h1b (DRAM x read,
//     prefetches x chunk into L2 for the NEXT launch's main part).
// Negative b0 disables that part (edge launches).
// ---------------------------------------------------------------------------
__global__ void __launch_bounds__(64) k_stage(
    const float* __restrict__ x, float* __restrict__ out,
    const float* __restrict__ a3p, const float* __restrict__ aoutp,
    int main_b0, int conv_b0)
{
    __shared__ uint32_t sh1[4][36];
    __shared__ uint32_t sw1[CI][4];
    __shared__ float sinv1[CI], sbb1[CI];
    __shared__ uint32_t sw2[CI][9];
    __shared__ float sinv2[CI], sbb2[CI];
    __shared__ uint32_t sw3[CC];
    __shared__ float sinv3[CC], sbb3[CC];

    int tid = threadIdx.x;

    if (blockIdx.x >= 1024) {
        // ---------------- CONV1 part ----------------
        if (conv_b0 < 0) return;
        if (tid < CI) {
            sinv1[tid] = g_inv1[tid]; sbb1[tid] = g_bb1[tid];
            #pragma unroll
            for (int j = 0; j < 4; j++) sw1[tid][j] = g_w1m[tid][j];
        }
        __syncthreads();

        int px = conv_b0 * HW + (int)(blockIdx.x - 1024) * 64 + tid;
        int b  = px / HW;
        int p  = px - b * HW;
        const float* xp = x + (size_t)b * (CC * HW) + p;

        uint32_t s0 = 0, s1 = 0, s2 = 0, s3 = 0;
        #pragma unroll
        for (int i = 0; i < 32; i++) {
            if (xp[(i      ) * HW] > 0.f) s0 |= (1u << i);
            if (xp[(i +  32) * HW] > 0.f) s1 |= (1u << i);
            if (xp[(i +  64) * HW] > 0.f) s2 |= (1u << i);
            if (xp[(i +  96) * HW] > 0.f) s3 |= (1u << i);
        }

        uint32_t outm = 0;
        #pragma unroll
        for (int oc = 0; oc < CI; oc++) {
            int pc = __popc(s0 ^ sw1[oc][0]) + __popc(s1 ^ sw1[oc][1])
                   + __popc(s2 ^ sw1[oc][2]) + __popc(s3 ^ sw1[oc][3]);
            float v = __fadd_rn(__fmul_rn((float)(128 - 2 * pc), sinv1[oc]), sbb1[oc]);
            if (v > 0.f) outm |= (1u << oc);
        }
        g_h1b[px] = outm;
        return;
    }

    // ---------------- MAIN part ----------------
    if (main_b0 < 0) return;

    if (tid < CI) {
        sinv2[tid] = g_inv2[tid]; sbb2[tid] = g_bb2[tid];
        #pragma unroll
        for (int t9 = 0; t9 < 9; t9++) sw2[tid][t9] = g_w2m[tid][t9];
    }
    #pragma unroll
    for (int c = tid; c < CC; c += 64) {
        sw3[c] = g_w3m[c]; sinv3[c] = g_inv3[c]; sbb3[c] = g_bb3[c];
    }

    // Tile decode: 512 tiles/batch (64 row-pairs x 8 col-strips of 32)
    int tb  = blockIdx.x;
    int b   = main_b0 + (tb >> 9);
    int rem = tb & 511;
    int ty0 = (rem >> 3) << 1;    // first of 2 rows
    int wx  = (rem & 7) << 5;     // col strip start

    // Halo: rows ty0-1..ty0+2, cols wx-1..wx+32 (4 x 34)
    const uint32_t* h1 = g_h1b + (size_t)b * HW;
    for (int it = tid; it < 4 * 34; it += 64) {
        int r = it / 34, c = it - r * 34;
        int gh = ty0 - 1 + r, gw = wx - 1 + c;
        uint32_t v = 0;
        if (gh >= 0 && gh < HH && gw >= 0 && gw < WW) v = h1[gh * WW + gw];
        sh1[r][c] = v;
    }
    __syncthreads();

    int tx  = tid & 31, tyl = tid >> 5;     // tyl in {0,1}
    int row = ty0 + tyl, col = wx + tx;

    // conv2: center at sh1[tyl+1][tx+1]; tap t -> sh1[tyl + t/3][tx + t%3]
    uint32_t n[9];
    #pragma unroll
    for (int t = 0; t < 9; t++)
        n[t] = sh1[tyl + t / 3][tx + t % 3];

    uint32_t h2b = 0;
    const bool interior = (row > 0) & (row < HH - 1) & (col > 0) & (col < WW - 1);
    if (interior) {
        #pragma unroll
        for (int oc = 0; oc < CI; oc++) {
            int pc = 0;
            #pragma unroll
            for (int t = 0; t < 9; t++) pc += __popc(n[t] ^ sw2[oc][t]);
            float v = __fadd_rn(__fmul_rn((float)(288 - 2 * pc), sinv2[oc]), sbb2[oc]);
            if (v > 0.f) h2b |= (1u << oc);
        }
    } else {
        bool ok[9];
        #pragma unroll
        for (int t = 0; t < 9; t++) {
            int yy = row + t / 3 - 1, xx = col + t % 3 - 1;
            ok[t] = (yy >= 0) & (yy < HH) & (xx >= 0) & (xx < WW);
        }
        #pragma unroll
        for (int oc = 0; oc < CI; oc++) {
            int z = 0;
            #pragma unroll
            for (int t = 0; t < 9; t++) {
                int c9 = 32 - 2 * __popc(n[t] ^ sw2[oc][t]);
                z += ok[t] ? c9 : 0;
            }
            float v = __fadd_rn(__fmul_rn((float)z, sinv2[oc]), sbb2[oc]);
            if (v > 0.f) h2b |= (1u << oc);
        }
    }

    // conv3 + bn + prelu + residual (x read = L2 hit) + prelu, __stwt store.
    float a3   = a3p[0];
    float aout = aoutp[0];
    size_t base = (size_t)b * (CC * HW) + (size_t)row * WW + col;
    const float* xp = x + base;
    float* op = out + base;

    #pragma unroll 16
    for (int c = 0; c < CC; c++) {
        int z = 32 - 2 * __popc(h2b ^ sw3[c]);
        float v = __fadd_rn(__fmul_rn((float)z, sinv3[c]), sbb3[c]);
        v = (v >= 0.f) ? v : a3 * v;
        float s = v + xp[(size_t)c * HW];
        s = (s >= 0.f) ? s : aout * s;
        __stwt(op + (size_t)c * HW, s);
    }
}

// ---------------------------------------------------------------------------
extern "C" void kernel_launch(void* const* d_in, const int* in_sizes, int n_in,
                              void* d_out, int out_size)
{
    const float* x  = (const float*)d_in[0];
    const float* w1 = (const float*)d_in[1];
    const float* g1 = (const float*)d_in[2];
    const float* b1 = (const float*)d_in[3];
    const float* m1 = (const float*)d_in[4];
    const float* v1 = (const float*)d_in[5];
    // d_in[6] = a1 (unused: prelu with a>0 never changes the following sign)
    const float* w2 = (const float*)d_in[7];
    const float* g2 = (const float*)d_in[8];
    const float* b2 = (const float*)d_in[9];
    const float* m2 = (const float*)d_in[10];
    const float* v2 = (const float*)d_in[11];
    // d_in[12] = a2 (unused, same reason)
    const float* w3 = (const float*)d_in[13];
    const float* g3 = (const float*)d_in[14];
    const float* b3 = (const float*)d_in[15];
    const float* m3 = (const float*)d_in[16];
    const float* v3 = (const float*)d_in[17];
    const float* a3 = (const float*)d_in[18];
    const float* ao = (const float*)d_in[19];
    float* out = (float*)d_out;

    prep_kernel<<<68, 256>>>(w1, g1, b1, m1, v1,
                             w2, g2, b2, m2, v2,
                             w3, g3, b3, m3, v3);

    // Software pipeline: launch k = main(batches 2k-2,2k-1) + conv1(2k,2k+1).
    // conv1(s+1)'s pure-read DRAM stream overlaps main(s)'s write stream,
    // and leaves x[s+1] in L2 for the next launch's main part.
    k_stage<<<2048, 64>>>(x, out, a3, ao, -1, 0);
    k_stage<<<2048, 64>>>(x, out, a3, ao,  0, 2);
    k_stage<<<2048, 64>>>(x, out, a3, ao,  2, 4);
    k_stage<<<2048, 64>>>(x, out, a3, ao,  4, 6);
    k_stage<<<2048, 64>>>(x, out, a3, ao,  6, -1);
}

// round 15
// speedup vs baseline: 1.5690x; 1.5690x over previous
#include <cuda_runtime.h>
#include <stdint.h>

#define CC   128
#define CI   32
#define HH   128
#define WW   256
#define BB   8
#define HW   (HH*WW)

// Published by block 0 of k_conv1 for k_main (k_main launches after).
__device__ uint32_t g_w2m[CI][9];
__device__ float    g_inv2[CI], g_bb2[CI];
__device__ uint32_t g_w3m[CC];
__device__ float    g_inv3[CC], g_bb3[CC];

// Scratch: h1 binarized activations, 32 channels packed per pixel. 1 MB.
__device__ uint32_t g_h1b[BB * HW];

// ---------------------------------------------------------------------------
// Kernel A: conv1 (1x1, 128->32) + bn + sign -> packed h1 bitmask per pixel.
// Self-contained: every block ballots w1 into smem (16 words/warp, one L2
// round-trip) and threads 0-31 fold bn1; block 0 additionally publishes
// w2/w3 masks + bn2/bn3 to globals for k_main. NO separate prep launch.
// ---------------------------------------------------------------------------
__global__ void __launch_bounds__(256) k_conv1(
    const float* __restrict__ x,
    const float* __restrict__ w1, const float* __restrict__ g1,
    const float* __restrict__ b1, const float* __restrict__ m1, const float* __restrict__ v1,
    const float* __restrict__ w2, const float* __restrict__ g2,
    const float* __restrict__ b2, const float* __restrict__ m2, const float* __restrict__ v2,
    const float* __restrict__ w3, const float* __restrict__ g3,
    const float* __restrict__ b3, const float* __restrict__ m3, const float* __restrict__ v3)
{
    __shared__ uint32_t sw1[CI][4];
    __shared__ float sinv1[CI], sbb1[CI];

    int tid  = threadIdx.x;
    int warp = tid >> 5;
    int lane = tid & 31;

    // w1 masks: 128 words, 16 per warp. bit c = (w > 0).
    #pragma unroll
    for (int k = 0; k < 16; k++) {
        int word = warp * 16 + k;
        int oc = word >> 2, j = word & 3;
        uint32_t m = __ballot_sync(0xffffffffu, w1[oc * CC + j * 32 + lane] > 0.f);
        if (lane == 0) sw1[oc][j] = m;
    }
    if (tid < CI) {
        float inv = __fdiv_rn(g1[tid], __fsqrt_rn(__fadd_rn(v1[tid], 1e-5f)));
        sinv1[tid] = inv;
        sbb1[tid]  = __fadd_rn(b1[tid], -__fmul_rn(m1[tid], inv));
    }

    // Block 0 publishes w2/w3 + bn2/bn3 for k_main (runs after this kernel).
    if (blockIdx.x == 0) {
        for (int word = warp; word < CI * 9; word += 8) {
            int oc = word / 9, t9 = word - oc * 9;
            uint32_t m = __ballot_sync(0xffffffffu, w2[oc * (CI * 9) + lane * 9 + t9] > 0.f);
            if (lane == 0) g_w2m[oc][t9] = m;
        }
        for (int word = warp; word < CC; word += 8) {
            uint32_t m = __ballot_sync(0xffffffffu, w3[word * CI + lane] > 0.f);
            if (lane == 0) g_w3m[word] = m;
        }
        if (tid < CI) {
            float inv = __fdiv_rn(g2[tid], __fsqrt_rn(__fadd_rn(v2[tid], 1e-5f)));
            g_inv2[tid] = inv;
            g_bb2[tid]  = __fadd_rn(b2[tid], -__fmul_rn(m2[tid], inv));
        }
        if (tid < CC) {
            float inv = __fdiv_rn(g3[tid], __fsqrt_rn(__fadd_rn(v3[tid], 1e-5f)));
            g_inv3[tid] = inv;
            g_bb3[tid]  = __fadd_rn(b3[tid], -__fmul_rn(m3[tid], inv));
        }
    }
    __syncthreads();

    int px = blockIdx.x * 256 + tid;     // 0 .. B*H*W-1 (exact multiple)
    int b  = px / HW;
    int p  = px - b * HW;
    const float* xp = x + (size_t)b * (CC * HW) + p;

    uint32_t s0 = 0, s1 = 0, s2 = 0, s3 = 0;
    #pragma unroll
    for (int i = 0; i < 32; i++) {
        if (xp[(i      ) * HW] > 0.f) s0 |= (1u << i);
        if (xp[(i +  32) * HW] > 0.f) s1 |= (1u << i);
        if (xp[(i +  64) * HW] > 0.f) s2 |= (1u << i);
        if (xp[(i +  96) * HW] > 0.f) s3 |= (1u << i);
    }

    uint32_t outm = 0;
    #pragma unroll
    for (int oc = 0; oc < CI; oc++) {
        int pc = __popc(s0 ^ sw1[oc][0]) + __popc(s1 ^ sw1[oc][1])
               + __popc(s2 ^ sw1[oc][2]) + __popc(s3 ^ sw1[oc][3]);
        float z = (float)(128 - 2 * pc);
        float v = __fadd_rn(__fmul_rn(z, sinv1[oc]), sbb1[oc]);
        if (v > 0.f) outm |= (1u << oc);
    }
    g_h1b[px] = outm;
}

// ---------------------------------------------------------------------------
// Kernel B: conv2 (3x3, zero-pad AFTER binarize) + conv3 (1x1, 32->128)
//           + bn + prelu + residual + prelu. Tile 32(W) x 8(H), 1 px/thread.
// (R9 champion verbatim; measured ~62us = mixed-stream ceiling.)
// ---------------------------------------------------------------------------
#define TW 32
#define TH 8

__global__ void __launch_bounds__(256) k_main(
    const float* __restrict__ x, float* __restrict__ out,
    const float* __restrict__ a3p, const float* __restrict__ aoutp)
{
    __shared__ uint32_t sh1[TH + 2][TW + 2];
    __shared__ uint32_t sw2[CI][9];
    __shared__ float sinv2[CI], sbb2[CI];
    __shared__ uint32_t sw3[CC];
    __shared__ float sinv3[CC], sbb3[CC];

    int tid = threadIdx.x;
    int tx = tid & (TW - 1);
    int ty = tid / TW;
    int w0 = blockIdx.x * TW;
    int h0 = blockIdx.y * TH;
    int b  = blockIdx.z;

    if (tid < CC) { sw3[tid] = g_w3m[tid]; sinv3[tid] = g_inv3[tid]; sbb3[tid] = g_bb3[tid]; }
    if (tid < CI) {
        sinv2[tid] = g_inv2[tid]; sbb2[tid] = g_bb2[tid];
        #pragma unroll
        for (int t9 = 0; t9 < 9; t9++) sw2[tid][t9] = g_w2m[tid][t9];
    }

    const bool border = (w0 == 0) | (h0 == 0) | (w0 + TW == WW) | (h0 + TH == HH);

    // Load h1 bitmask tile + 1-pixel halo
    const uint32_t* h1b = g_h1b + (size_t)b * HW;
    for (int it = tid; it < (TH + 2) * (TW + 2); it += 256) {
        int hy = it / (TW + 2), hx = it - hy * (TW + 2);
        int gh = h0 + hy - 1, gw = w0 + hx - 1;
        uint32_t v = 0;
        if (gh >= 0 && gh < HH && gw >= 0 && gw < WW) v = h1b[gh * WW + gw];
        sh1[hy][hx] = v;
    }
    __syncthreads();

    int gh = h0 + ty, gw = w0 + tx;

    // conv2 neighborhood masks: center at sh1[ty+1][tx+1]; tap t offset
    // (t/3-1, t%3-1) -> gather sh1[ty + t/3][tx + t%3].
    uint32_t n[9];
    #pragma unroll
    for (int t = 0; t < 9; t++)
        n[t] = sh1[ty + t / 3][tx + t % 3];

    uint32_t h2b = 0;
    if (!border) {
        // Interior: all 9 taps valid -> z = 288 - 2 * sum(popc)
        #pragma unroll
        for (int oc = 0; oc < CI; oc++) {
            int pc = 0;
            #pragma unroll
            for (int t = 0; t < 9; t++) pc += __popc(n[t] ^ sw2[oc][t]);
            float v = __fadd_rn(__fmul_rn((float)(288 - 2 * pc), sinv2[oc]), sbb2[oc]);
            if (v > 0.f) h2b |= (1u << oc);
        }
    } else {
        bool ok[9];
        #pragma unroll
        for (int t = 0; t < 9; t++) {
            int yy = gh + t / 3 - 1, xx = gw + t % 3 - 1;
            ok[t] = (yy >= 0) & (yy < HH) & (xx >= 0) & (xx < WW);
        }
        #pragma unroll
        for (int oc = 0; oc < CI; oc++) {
            int z = 0;
            #pragma unroll
            for (int t = 0; t < 9; t++) {
                int c9 = 32 - 2 * __popc(n[t] ^ sw2[oc][t]);
                z += ok[t] ? c9 : 0;
            }
            float v = __fadd_rn(__fmul_rn((float)z, sinv2[oc]), sbb2[oc]);
            if (v > 0.f) h2b |= (1u << oc);
        }
    }

    // conv3 + bn + prelu + residual + prelu
    float a3   = a3p[0];
    float aout = aoutp[0];
    size_t base = (size_t)b * (CC * HW) + (size_t)gh * WW + gw;
    const float* xp = x + base;
    float* op = out + base;

    #pragma unroll 16
    for (int c = 0; c < CC; c++) {
        int z = 32 - 2 * __popc(h2b ^ sw3[c]);
        float v = __fadd_rn(__fmul_rn((float)z, sinv3[c]), sbb3[c]);
        v = (v >= 0.f) ? v : a3 * v;
        float s = v + xp[(size_t)c * HW];
        s = (s >= 0.f) ? s : aout * s;
        __stwt(op + (size_t)c * HW, s);
    }
}

// ---------------------------------------------------------------------------
extern "C" void kernel_launch(void* const* d_in, const int* in_sizes, int n_in,
                              void* d_out, int out_size)
{
    const float* x  = (const float*)d_in[0];
    const float* w1 = (const float*)d_in[1];
    const float* g1 = (const float*)d_in[2];
    const float* b1 = (const float*)d_in[3];
    const float* m1 = (const float*)d_in[4];
    const float* v1 = (const float*)d_in[5];
    // d_in[6] = a1 (unused: prelu with a>0 never changes the following sign)
    const float* w2 = (const float*)d_in[7];
    const float* g2 = (const float*)d_in[8];
    const float* b2 = (const float*)d_in[9];
    const float* m2 = (const float*)d_in[10];
    const float* v2 = (const float*)d_in[11];
    // d_in[12] = a2 (unused, same reason)
    const float* w3 = (const float*)d_in[13];
    const float* g3 = (const float*)d_in[14];
    const float* b3 = (const float*)d_in[15];
    const float* m3 = (const float*)d_in[16];
    const float* v3 = (const float*)d_in[17];
    const float* a3 = (const float*)d_in[18];
    const float* ao = (const float*)d_in[19];
    float* out = (float*)d_out;

    // Two launches total: conv1 self-preps all weight masks (block 0
    // publishes w2/w3 for k_main); k_main runs after.
    k_conv1<<<(BB * HW) / 256, 256>>>(x,
                                      w1, g1, b1, m1, v1,
                                      w2, g2, b2, m2, v2,
                                      w3, g3, b3, m3, v3);

    dim3 grid(WW / TW, HH / TH, BB);   // 8 x 16 x 8 = 1024 blocks
    k_main<<<grid, 256>>>(x, out, a3, ao);
}